// round 1
// baseline (speedup 1.0000x reference)
#include <cuda_runtime.h>
#include <cstdint>

#define SEQ 2048
#define NB 64
#define NF 16
#define HD 512
#define SLOT_PAD 516   // 516*16B-units per f-row -> stride 129 (odd) in 16B units: conflict-free LDS.128

// Scratch (allocation-free rule: __device__ globals)
__device__ int g_list[NB * SEQ];   // packed: s | (seg << 16), compacted per batch
__device__ int g_cnt[NB];

__device__ __forceinline__ unsigned long long ffma2(unsigned long long a,
                                                    unsigned long long b,
                                                    unsigned long long c) {
    unsigned long long d;
    asm("fma.rn.f32x2 %0, %1, %2, %3;" : "=l"(d) : "l"(a), "l"(b), "l"(c));
    return d;
}

// ---------------------------------------------------------------------------
// Kernel 0: zero the output (harness poisons it with 0xAA)
// ---------------------------------------------------------------------------
__global__ void zero_kernel(float* __restrict__ out, int n) {
    int i = blockIdx.x * blockDim.x + threadIdx.x;
    if (i < n) out[i] = 0.0f;
}

// ---------------------------------------------------------------------------
// Block-wide exclusive scan over 256 threads (caller syncs between uses)
// ---------------------------------------------------------------------------
__device__ __forceinline__ int block_exscan(int v, int* sh) {
    int lane = threadIdx.x & 31;
    int w = threadIdx.x >> 5;
    int incl = v;
#pragma unroll
    for (int o = 1; o < 32; o <<= 1) {
        int n = __shfl_up_sync(0xFFFFFFFFu, incl, o);
        if (lane >= o) incl += n;
    }
    if (lane == 31) sh[w] = incl;
    __syncthreads();
    if (threadIdx.x < 8) {
        int x = sh[threadIdx.x];
#pragma unroll
        for (int o = 1; o < 8; o <<= 1) {
            int n = __shfl_up_sync(0xFFu, x, o);
            if (threadIdx.x >= (unsigned)o) x += n;
        }
        sh[threadIdx.x] = x;
    }
    __syncthreads();
    int wofs = (w == 0) ? 0 : sh[w - 1];
    return wofs + incl - v;
}

// ---------------------------------------------------------------------------
// Kernel 1: per-batch span ids (cumsum of isB - 1) + deterministic compaction
// of valid tokens ((isB|isI) && 0 <= seg < max_spans).
// One block per batch row, 256 threads x 8 tokens each.
// ---------------------------------------------------------------------------
__global__ __launch_bounds__(256) void seg_kernel(const int* __restrict__ labels,
                                                  const int* pB, const int* pI,
                                                  const int* pMS) {
    __shared__ int sh[8];
    int b = blockIdx.x;
    int t = threadIdx.x;
    int Bv = pB ? *pB : 1;
    int Iv = pI ? *pI : 2;
    int MS = pMS ? *pMS : 512;

    const int4* row = reinterpret_cast<const int4*>(labels + b * SEQ) + t * 2;
    int4 a = row[0];
    int4 c = row[1];
    int lab[8] = {a.x, a.y, a.z, a.w, c.x, c.y, c.z, c.w};

    int incl[8];
    int csum = 0;
#pragma unroll
    for (int i = 0; i < 8; i++) {
        csum += (lab[i] == Bv);
        incl[i] = csum;
    }
    int ex = block_exscan(csum, sh);

    int seg[8], vfl[8];
    int vtot = 0;
#pragma unroll
    for (int i = 0; i < 8; i++) {
        seg[i] = ex + incl[i] - 1;
        vfl[i] = ((lab[i] == Bv) || (lab[i] == Iv)) && seg[i] >= 0 && seg[i] < MS;
        vtot += vfl[i];
    }
    __syncthreads();  // sh reuse barrier
    int vex = block_exscan(vtot, sh);

    int pos = vex;
#pragma unroll
    for (int i = 0; i < 8; i++) {
        if (vfl[i]) {
            g_list[b * SEQ + pos] = (t * 8 + i) | (seg[i] << 16);
            pos++;
        }
    }
    if (t == 255) g_cnt[b] = vex + vtot;
}

// ---------------------------------------------------------------------------
// Kernel 2: for each valid token, project its hidden row (512 f32) onto the
// 16 slot embeddings and atomically scatter into out[b, seg, f].
//
// Layout: 256 threads = 8 warps, 16 tokens/warp, 128 tokens/block.
//   lane = g*8 + fh : g in 0..3 token group (4 tokens each), fh in 0..7.
//   Lane owns f = {fh, fh+8} for its group's 4 tokens -> 8 accumulators,
//   each an f32x2 pair accumulating (even-d, odd-d) partials so that
//   ulonglong2 loads of hidden/slot feed fma.rn.f32x2 with zero packing cost.
// slot_embs staged transposed in smem: sh[f][d], row pad 516 (conflict-free).
// ---------------------------------------------------------------------------
__global__ __launch_bounds__(256) void proj_kernel(const float* __restrict__ hidden,
                                                   const float* __restrict__ slot,
                                                   const int* pMS,
                                                   float* __restrict__ out) {
    int b = blockIdx.y;
    int cnt = g_cnt[b];
    int tok0 = blockIdx.x * 128;
    if (tok0 >= cnt) return;
    int MS = pMS ? *pMS : 512;

    __shared__ float sh[NF * SLOT_PAD];
    for (int i = threadIdx.x; i < HD * NF; i += 256) {
        int d = i >> 4;
        int f = i & 15;
        sh[f * SLOT_PAD + d] = slot[i];
    }
    __syncthreads();

    int w = threadIdx.x >> 5;
    int lane = threadIdx.x & 31;
    int g = lane >> 3;
    int fh = lane & 7;
    int tbase = tok0 + w * 16 + g * 4;

    const float* base = hidden + (size_t)b * SEQ * HD;
    const float* rows[4];
    int segs[4];
    bool val[4];
#pragma unroll
    for (int j = 0; j < 4; j++) {
        int ti = tbase + j;
        bool v = ti < cnt;
        int p = v ? g_list[b * SEQ + ti] : 0;
        int s = p & 0xFFFF;
        segs[j] = p >> 16;
        rows[j] = base + (size_t)s * HD;
        val[j] = v;
    }

    const float* sp0 = sh + fh * SLOT_PAD;
    const float* sp1 = sh + (fh + 8) * SLOT_PAD;

    unsigned long long acc[4][2];
#pragma unroll
    for (int j = 0; j < 4; j++) {
        acc[j][0] = 0ull;
        acc[j][1] = 0ull;
    }

#pragma unroll 4
    for (int d = 0; d < HD; d += 4) {
        ulonglong2 s0 = *reinterpret_cast<const ulonglong2*>(sp0 + d);
        ulonglong2 s1 = *reinterpret_cast<const ulonglong2*>(sp1 + d);
#pragma unroll
        for (int j = 0; j < 4; j++) {
            ulonglong2 h = *reinterpret_cast<const ulonglong2*>(rows[j] + d);
            acc[j][0] = ffma2(h.x, s0.x, acc[j][0]);
            acc[j][0] = ffma2(h.y, s0.y, acc[j][0]);
            acc[j][1] = ffma2(h.x, s1.x, acc[j][1]);
            acc[j][1] = ffma2(h.y, s1.y, acc[j][1]);
        }
    }

#pragma unroll
    for (int j = 0; j < 4; j++) {
        if (!val[j]) continue;
        float* op = out + ((size_t)b * MS + segs[j]) * NF;
        float2 v0 = *reinterpret_cast<float2*>(&acc[j][0]);
        float2 v1 = *reinterpret_cast<float2*>(&acc[j][1]);
        atomicAdd(op + fh, v0.x + v0.y);
        atomicAdd(op + fh + 8, v1.x + v1.y);
    }
}

// ---------------------------------------------------------------------------
extern "C" void kernel_launch(void* const* d_in, const int* in_sizes, int n_in,
                              void* d_out, int out_size) {
    const float* hidden = (const float*)d_in[0];
    const float* slot = (const float*)d_in[1];
    const int* labels = (const int*)d_in[2];
    const int* pB = (n_in > 3) ? (const int*)d_in[3] : nullptr;
    const int* pI = (n_in > 4) ? (const int*)d_in[4] : nullptr;
    const int* pMS = (n_in > 5) ? (const int*)d_in[5] : nullptr;
    float* out = (float*)d_out;

    zero_kernel<<<(out_size + 255) / 256, 256>>>(out, out_size);
    seg_kernel<<<NB, 256>>>(labels, pB, pI, pMS);
    proj_kernel<<<dim3(16, NB), 256>>>(hidden, slot, pMS, out);
}